// round 4
// baseline (speedup 1.0000x reference)
#include <cuda_runtime.h>
#include <cstdint>
#include <cstddef>

#define B_   8
#define C_   192
#define HW_  16384
#define D_   64

// ---------------- static device scratch (allocation-free rule) ----------------
__device__ float g_G[(size_t)B_ * HW_ * 192];      // gate pre-activations [b][p][192]
__device__ float g_Hp[4][(size_t)B_ * HW_ * D_];   // per-direction hidden: hF,hB,vF,vB
__device__ float g_Wc[C_ * 192];                   // Wc stored [c][g]
__device__ float g_bc[192];
__device__ float g_Wot[D_ * C_];                   // Wo^T stored [d][c]

__device__ __forceinline__ float sigm(float x) { return 1.f / (1.f + __expf(-x)); }

// ---------------- kernel 1: fold weights ----------------
// blocks 0..191  : g = bid; thread c: Wc[c][g] = sum_d W_ih[g][d]*Wi[d][c]
//                  thread 0 also bc[g] = W_ih[g]·bi + b_ih[g]
// blocks 192..255: d = bid-192; thread c: Wot[d][c] = Wo[c][d]
__global__ void prep_kernel(const float* __restrict__ Wi, const float* __restrict__ bi,
                            const float* __restrict__ Wih, const float* __restrict__ bih,
                            const float* __restrict__ Wo) {
    const int bid = blockIdx.x;
    const int c = threadIdx.x;
    if (bid < 192) {
        const int g = bid;
        float acc = 0.f;
        #pragma unroll 8
        for (int d = 0; d < 64; d++) acc += Wih[g * 64 + d] * Wi[d * 192 + c];
        g_Wc[c * 192 + g] = acc;
        if (c == 0) {
            float s = bih[g];
            for (int d = 0; d < 64; d++) s += Wih[g * 64 + d] * bi[d];
            g_bc[g] = s;
        }
    } else {
        const int d = bid - 192;
        g_Wot[d * 192 + c] = Wo[c * 64 + d];
    }
}

// ---------------- kernel 2: G = Wc @ x + bc ----------------
// block tile: 128 pixels x 64 gates, K=192 in chunks of 16. 256 threads (16x16),
// thread tile 8 px x 4 gates.
__global__ void __launch_bounds__(256) g_gemm_kernel(const float* __restrict__ x) {
    const int bx = blockIdx.x;            // 0..1023
    const int b  = bx >> 7;
    const int p0 = (bx & 127) * 128;
    const int g0 = blockIdx.y * 64;
    const int tid = threadIdx.x;
    const int tx = tid & 15;              // gate group
    const int ty = tid >> 4;              // pixel group

    __shared__ float sX[16][128];
    __shared__ float sW[16][64];

    float acc[8][4];
    #pragma unroll
    for (int i = 0; i < 8; i++)
        #pragma unroll
        for (int j = 0; j < 4; j++) acc[i][j] = 0.f;

    const float* xb = x + (size_t)b * C_ * HW_;

    for (int c0 = 0; c0 < 192; c0 += 16) {
        #pragma unroll
        for (int i = 0; i < 8; i++) {
            int lin = tid + i * 256;
            int cc = lin >> 7, pp = lin & 127;
            sX[cc][pp] = xb[(size_t)(c0 + cc) * HW_ + p0 + pp];
        }
        #pragma unroll
        for (int i = 0; i < 4; i++) {
            int lin = tid + i * 256;
            int cc = lin >> 6, gg = lin & 63;
            sW[cc][gg] = g_Wc[(c0 + cc) * 192 + g0 + gg];
        }
        __syncthreads();
        #pragma unroll
        for (int cc = 0; cc < 16; cc++) {
            float a[8], w[4];
            #pragma unroll
            for (int i = 0; i < 8; i++) a[i] = sX[cc][ty * 8 + i];
            #pragma unroll
            for (int j = 0; j < 4; j++) w[j] = sW[cc][tx * 4 + j];
            #pragma unroll
            for (int i = 0; i < 8; i++)
                #pragma unroll
                for (int j = 0; j < 4; j++) acc[i][j] += a[i] * w[j];
        }
        __syncthreads();
    }

    float bc[4];
    #pragma unroll
    for (int j = 0; j < 4; j++) bc[j] = g_bc[g0 + tx * 4 + j];

    #pragma unroll
    for (int i = 0; i < 8; i++) {
        const size_t pix = (size_t)b * HW_ + p0 + ty * 8 + i;
        float4 v = make_float4(acc[i][0] + bc[0], acc[i][1] + bc[1],
                               acc[i][2] + bc[2], acc[i][3] + bc[3]);
        *(float4*)&g_G[pix * 192 + g0 + tx * 4] = v;
    }
}

// ---------------- kernel 3: GRU scans ----------------
// 2048 blocks: [0,1024) horizontal lines, [1024,2048) vertical lines.
// 192 threads; thread g holds W_hh row g in registers. fwd+bwd run together.
__global__ void __launch_bounds__(192) scan_kernel(const float* __restrict__ Whh,
                                                   const float* __restrict__ bhh) {
    const int l    = blockIdx.x;
    const int axis = l >> 10;             // 0 horiz, 1 vert
    const int ll   = l & 1023;
    const int b    = ll >> 7;
    const int lane = ll & 127;            // row (horiz) or col (vert)
    const int g    = threadIdx.x;

    __shared__ float h[2][64];            // [dir][d]
    __shared__ float hg[2][192];          // [dir][g]

    float wrow[64];
    #pragma unroll
    for (int d = 0; d < 64; d++) wrow[d] = Whh[g * 64 + d];
    const float bh = bhh[g];

    if (g < 64) { h[0][g] = 0.f; h[1][g] = 0.f; }
    __syncthreads();

    const float* Gb  = g_G + (size_t)b * HW_ * 192;
    float* outF = g_Hp[axis * 2 + 0] + (size_t)b * HW_ * 64;
    float* outB = g_Hp[axis * 2 + 1] + (size_t)b * HW_ * 64;
    const int pstride = axis ? 128 : 1;
    const int pbase   = axis ? lane : lane * 128;

    for (int t = 0; t < 128; t++) {
        float af = bh, ab = bh;
        #pragma unroll
        for (int d = 0; d < 64; d++) {
            af += wrow[d] * h[0][d];
            ab += wrow[d] * h[1][d];
        }
        hg[0][g] = af;
        hg[1][g] = ab;
        __syncthreads();
        if (g < 128) {
            const int dir = g >> 6;                 // 0 fwd, 1 bwd
            const int d   = g & 63;
            const int tt  = dir ? (127 - t) : t;    // input/output position
            const int p   = pbase + tt * pstride;
            const float* Gp = Gb + (size_t)p * 192;
            const float xr = Gp[d], xz = Gp[64 + d], xn = Gp[128 + d];
            const float hr = hg[dir][d], hz = hg[dir][64 + d], hn = hg[dir][128 + d];
            const float r = sigm(xr + hr);
            const float z = sigm(xz + hz);
            const float pre = xn + r * hn;
            const float n = 2.f / (1.f + __expf(-2.f * pre)) - 1.f;   // tanh
            const float hnew = (1.f - z) * n + z * h[dir][d];
            h[dir][d] = hnew;
            (dir ? outB : outF)[(size_t)p * 64 + d] = hnew;
        }
        __syncthreads();
    }
}

// ---------------- kernel 4: out = Wo @ (sum4(h)/4) + bo ----------------
// block tile: 64 pixels x 64 channels, K=64 (full). 256 threads (16x16),
// thread tile 4 px x 4 channels.
__global__ void __launch_bounds__(256) out_gemm_kernel(const float* __restrict__ bo,
                                                       float* __restrict__ out) {
    const int bx = blockIdx.x;            // 0..2047
    const int b  = bx >> 8;
    const int p0 = (bx & 255) * 64;
    const int c0 = blockIdx.y * 64;
    const int tid = threadIdx.x;
    const int tx = tid & 15;              // channel group
    const int ty = tid >> 4;              // pixel group

    __shared__ float sH[64][65];          // [pixel][d], padded
    __shared__ float sW[64][64];          // [d][channel]

    const size_t base = ((size_t)b * HW_ + p0) * 64;
    const float* h0 = g_Hp[0] + base;
    const float* h1 = g_Hp[1] + base;
    const float* h2 = g_Hp[2] + base;
    const float* h3 = g_Hp[3] + base;

    #pragma unroll
    for (int i = 0; i < 16; i++) {
        int lin = tid + i * 256;          // 4096 elems
        int pp = lin >> 6, dd = lin & 63;
        size_t idx = (size_t)pp * 64 + dd;
        sH[pp][dd] = 0.25f * (h0[idx] + h1[idx] + h2[idx] + h3[idx]);
    }
    #pragma unroll
    for (int i = 0; i < 16; i++) {
        int lin = tid + i * 256;
        int dd = lin >> 6, cc = lin & 63;
        sW[dd][cc] = g_Wot[dd * 192 + c0 + cc];
    }
    __syncthreads();

    float acc[4][4];
    #pragma unroll
    for (int i = 0; i < 4; i++)
        #pragma unroll
        for (int j = 0; j < 4; j++) acc[i][j] = 0.f;

    #pragma unroll
    for (int dd = 0; dd < 64; dd++) {
        float a[4], w[4];
        #pragma unroll
        for (int i = 0; i < 4; i++) a[i] = sH[ty * 4 + i][dd];
        #pragma unroll
        for (int j = 0; j < 4; j++) w[j] = sW[dd][tx * 4 + j];
        #pragma unroll
        for (int i = 0; i < 4; i++)
            #pragma unroll
            for (int j = 0; j < 4; j++) acc[i][j] += a[i] * w[j];
    }

    #pragma unroll
    for (int j = 0; j < 4; j++) {
        const int c = c0 + tx * 4 + j;
        const float bv = bo[c];
        float4 v = make_float4(acc[0][j] + bv, acc[1][j] + bv,
                               acc[2][j] + bv, acc[3][j] + bv);
        *(float4*)&out[((size_t)b * 192 + c) * HW_ + p0 + ty * 4] = v;
    }
}

// ---------------- launch ----------------
extern "C" void kernel_launch(void* const* d_in, const int* in_sizes, int n_in,
                              void* d_out, int out_size) {
    const float* x   = (const float*)d_in[0];
    const float* Wi  = (const float*)d_in[1];
    const float* bi  = (const float*)d_in[2];
    const float* Wih = (const float*)d_in[3];
    const float* Whh = (const float*)d_in[4];
    const float* bih = (const float*)d_in[5];
    const float* bhh = (const float*)d_in[6];
    const float* Wo  = (const float*)d_in[7];
    const float* bo  = (const float*)d_in[8];
    float* out = (float*)d_out;

    prep_kernel<<<256, 192>>>(Wi, bi, Wih, bih, Wo);
    g_gemm_kernel<<<dim3(1024, 3), 256>>>(x);
    scan_kernel<<<2048, 192>>>(Whh, bhh);
    out_gemm_kernel<<<dim3(2048, 3), 256>>>(bo, out);
}